// round 17
// baseline (speedup 1.0000x reference)
#include <cuda_runtime.h>
#include <cstdint>

#define SQ 2048
#define BB 2
#define HH 16
#define DD 64
#define STRIDEF (BB * HH * DD)   // 2048 floats between consecutive seq positions
#define MT 256                   // q rows per CTA (8 warps x M=32)
#define NT 64                    // keys per tile
#define NTILES (SQ / NT)
#define NTHREADS 256
#define SSTR 68                  // smem row stride in 4B words (padding vs banks)

// Q pre-scale: 1/sqrt(64) * log2(e), so softmax is a bare ex2
#define QSCALE (0.125f * 1.4426950408889634f)

__device__ __forceinline__ uint32_t f2tf32(float f) {
    uint32_t u;
    asm("cvt.rna.tf32.f32 %0, %1;" : "=r"(u) : "f"(f));
    return u;
}

__device__ __forceinline__ float ex2f(float x) {
    float y;
    asm("ex2.approx.f32 %0, %1;" : "=f"(y) : "f"(x));
    return y;
}

#define MMA_TF32(d, a0, a1, a2, a3, b0, b1)                                       \
    asm volatile(                                                                 \
        "mma.sync.aligned.m16n8k8.row.col.f32.tf32.tf32.f32 "                     \
        "{%0,%1,%2,%3}, {%4,%5,%6,%7}, {%8,%9}, {%0,%1,%2,%3};"                   \
        : "+f"(d[0]), "+f"(d[1]), "+f"(d[2]), "+f"(d[3])                          \
        : "r"(a0), "r"(a1), "r"(a2), "r"(a3), "r"(b0), "r"(b1))

// first k-step: C = 0 (saves explicit zero-init of the accumulator)
#define MMA_TF32_Z(d, a0, a1, a2, a3, b0, b1)                                     \
    asm volatile(                                                                 \
        "mma.sync.aligned.m16n8k8.row.col.f32.tf32.tf32.f32 "                     \
        "{%0,%1,%2,%3}, {%4,%5,%6,%7}, {%8,%9}, {%10,%10,%10,%10};"               \
        : "=f"(d[0]), "=f"(d[1]), "=f"(d[2]), "=f"(d[3])                          \
        : "r"(a0), "r"(a1), "r"(a2), "r"(a3), "r"(b0), "r"(b1), "f"(0.0f))

__global__ __launch_bounds__(NTHREADS, 1) void dpa_mma_kernel(
    const float* __restrict__ q,
    const float* __restrict__ k,
    const float* __restrict__ v,
    const unsigned char* __restrict__ mask,
    float* __restrict__ out)
{
    // 128 rows x SSTR words: used as [Q-staging pass buffer], then [K(64) | V(64)]
    __shared__ uint32_t smbuf[2 * NT * SSTR];
    uint32_t* const ksm = smbuf;
    uint32_t* const vsm = smbuf + NT * SSTR;

    const int tid = threadIdx.x;
    const int w = tid >> 5;        // 0..7
    const int lane = tid & 31;
    const int r = lane >> 2;       // 0..7
    const int c = lane & 3;        // 0..3
    const int bh = blockIdx.y;
    const int qbase = blockIdx.x * MT;

    const float* qg = q + (size_t)bh * DD;
    const float* kg = k + (size_t)bh * DD;
    const float* vg = v + (size_t)bh * DD;
    float* og = out + (size_t)bh * DD;
    const unsigned char* mbase = mask + (size_t)bh * SQ * SQ;

    // ---- stage Q in two 128-row passes; each warp extracts its A-fragments ----
    // QK k-permutation: fragment position c <-> column 2c, position c+4 <-> 2c+1.
    // Applied identically to A (here) and B (mainloop) => S unchanged.
    uint32_t a[2][8][4];
#pragma unroll
    for (int p = 0; p < 2; p++) {
#pragma unroll
        for (int it = 0; it < 8; it++) {
            int idx = it * NTHREADS + tid;
            int row = idx >> 4, c4 = idx & 15;
            float4 t = *(const float4*)(qg +
                (size_t)(qbase + p * 128 + row) * STRIDEF + 4 * c4);
            uint4 u;
            u.x = f2tf32(t.x * QSCALE);
            u.y = f2tf32(t.y * QSCALE);
            u.z = f2tf32(t.z * QSCALE);
            u.w = f2tf32(t.w * QSCALE);
            *(uint4*)(smbuf + row * SSTR + 4 * c4) = u;
        }
        __syncthreads();
        if ((w >> 2) == p) {
            int rowb0 = 32 * (w & 3) * SSTR;
#pragma unroll
            for (int mt = 0; mt < 2; mt++) {
                int rowb = rowb0 + 16 * mt * SSTR;
#pragma unroll
                for (int kgi = 0; kgi < 8; kgi++) {
                    uint2 t0 = *(const uint2*)(smbuf + rowb + r * SSTR + 8 * kgi + 2 * c);
                    uint2 t1 = *(const uint2*)(smbuf + rowb + (8 + r) * SSTR + 8 * kgi + 2 * c);
                    a[mt][kgi][0] = t0.x;   // position c      <- col 2c
                    a[mt][kgi][2] = t0.y;   // position c+4    <- col 2c+1
                    a[mt][kgi][1] = t1.x;
                    a[mt][kgi][3] = t1.y;
                }
            }
        }
        __syncthreads();
    }

    // ---- preload K/V tile 0 into registers (4 float4 each) ----
    float4 pk[4], pv[4];
#pragma unroll
    for (int it = 0; it < 4; it++) {
        int idx = it * NTHREADS + tid;
        int row = idx >> 4, c4 = idx & 15;
        size_t go = (size_t)row * STRIDEF + 4 * c4;
        pk[it] = *(const float4*)(kg + go);
        pv[it] = *(const float4*)(vg + go);
    }

    float o[2][8][4];
#pragma unroll
    for (int mt = 0; mt < 2; mt++)
#pragma unroll
        for (int dn = 0; dn < 8; dn++)
#pragma unroll
            for (int e = 0; e < 4; e++) o[mt][dn][e] = 0.f;
    float lsum[4] = {0.f, 0.f, 0.f, 0.f};

#pragma unroll 1
    for (int t = 0; t < NTILES; t++) {
        const int j0 = t * NT;

        __syncthreads();   // previous tile's smem reads complete

        // ---- STS staged tile t from prefetch registers (tf32 RNA) ----
#pragma unroll
        for (int it = 0; it < 4; it++) {
            int idx = it * NTHREADS + tid;
            int row = idx >> 4, c4 = idx & 15;
            uint4 uk;
            uk.x = f2tf32(pk[it].x); uk.y = f2tf32(pk[it].y);
            uk.z = f2tf32(pk[it].z); uk.w = f2tf32(pk[it].w);
            *(uint4*)(ksm + row * SSTR + 4 * c4) = uk;
            uint4 uv;
            uv.x = f2tf32(pv[it].x); uv.y = f2tf32(pv[it].y);
            uv.z = f2tf32(pv[it].z); uv.w = f2tf32(pv[it].w);
            *(uint4*)(vsm + row * SSTR + 4 * c4) = uv;
        }
        __syncthreads();   // tile t visible

        // ---- prefetch tile t+1 (latency hidden behind compute below) ----
        {
            int tn = (t + 1 < NTILES) ? t + 1 : t;
            const float* kgt = kg + (size_t)(tn * NT) * STRIDEF;
            const float* vgt = vg + (size_t)(tn * NT) * STRIDEF;
#pragma unroll
            for (int it = 0; it < 4; it++) {
                int idx = it * NTHREADS + tid;
                int row = idx >> 4, c4 = idx & 15;
                size_t go = (size_t)row * STRIDEF + 4 * c4;
                pk[it] = *(const float4*)(kgt + go);
                pv[it] = *(const float4*)(vgt + go);
            }
        }

        // ---- mask quick-check: lane covers row (32w + lane), 64 bytes ----
        unsigned morr;
        {
            const uint4* mp = (const uint4*)(mbase +
                (size_t)(qbase + 32 * w + lane) * SQ + j0);
            uint4 m0 = mp[0], m1 = mp[1], m2 = mp[2], m3 = mp[3];
            morr = m0.x | m0.y | m0.z | m0.w | m1.x | m1.y | m1.z | m1.w |
                   m2.x | m2.y | m2.z | m2.w | m3.x | m3.y | m3.z | m3.w;
        }
        const bool anym = __any_sync(0xffffffffu, morr != 0u);

        // ---- pipelined jn loop: QK(jn+1) issued before exp(jn) / PV(jn) ----
        // one QK column-block: s[mt][:] = Q(32 rows) . K[8jn..8jn+7]^T
        float s[2][2][4];   // ping-pong on jn&1

#define QK_STEP(buf, jn_)                                                          \
        do {                                                                       \
            {                                                                      \
                uint2 bp = *(const uint2*)(ksm + (8 * (jn_) + r) * SSTR + 2 * c);  \
                MMA_TF32_Z(s[buf][0], a[0][0][0], a[0][0][1], a[0][0][2],          \
                           a[0][0][3], bp.x, bp.y);                                \
                MMA_TF32_Z(s[buf][1], a[1][0][0], a[1][0][1], a[1][0][2],          \
                           a[1][0][3], bp.x, bp.y);                                \
            }                                                                      \
            _Pragma("unroll")                                                      \
            for (int kgi = 1; kgi < 8; kgi++) {                                    \
                uint2 bp = *(const uint2*)(ksm + (8 * (jn_) + r) * SSTR +          \
                                           8 * kgi + 2 * c);                       \
                MMA_TF32(s[buf][0], a[0][kgi][0], a[0][kgi][1], a[0][kgi][2],      \
                         a[0][kgi][3], bp.x, bp.y);                                \
                MMA_TF32(s[buf][1], a[1][kgi][0], a[1][kgi][1], a[1][kgi][2],      \
                         a[1][kgi][3], bp.x, bp.y);                                \
            }                                                                      \
        } while (0)

        QK_STEP(0, 0);

#pragma unroll
        for (int jn = 0; jn < 8; jn++) {
            const int cur = jn & 1;
            if (jn < 7) QK_STEP(cur ^ 1, jn + 1);   // fills tensor pipe during exp

            // exp + mask + lsum + tf32 RNA on s[cur]
#pragma unroll
            for (int mt = 0; mt < 2; mt++) {
#pragma unroll
                for (int e = 0; e < 4; e++) {
                    float p = ex2f(s[cur][mt][e]);
                    if (anym) {
                        int row = qbase + 32 * w + 16 * mt + 8 * (e >> 1) + r;
                        int col = j0 + 8 * jn + 2 * c + (e & 1);
                        if (mbase[(size_t)row * SQ + col]) p = 0.f;
                    }
                    lsum[mt * 2 + (e >> 1)] += p;
                    s[cur][mt][e] = __uint_as_float(f2tf32(p));
                }
            }

            // PV: O += P[:, 8jn..8jn+7] @ V[8jn..8jn+7, :]
            // (k-permutation sigma: A-frag = {c0,c2,c1,c3}; B rows 8jn+2c, +2c+1)
#pragma unroll
            for (int dn = 0; dn < 8; dn++) {
                uint32_t b0 = vsm[(8 * jn + 2 * c) * SSTR + 8 * dn + r];
                uint32_t b1 = vsm[(8 * jn + 2 * c + 1) * SSTR + 8 * dn + r];
                MMA_TF32(o[0][dn],
                         __float_as_uint(s[cur][0][0]), __float_as_uint(s[cur][0][2]),
                         __float_as_uint(s[cur][0][1]), __float_as_uint(s[cur][0][3]),
                         b0, b1);
                MMA_TF32(o[1][dn],
                         __float_as_uint(s[cur][1][0]), __float_as_uint(s[cur][1][2]),
                         __float_as_uint(s[cur][1][1]), __float_as_uint(s[cur][1][3]),
                         b0, b1);
            }
        }
#undef QK_STEP
    }

    // ---- finalize: reduce row sums across the lane quad, normalize, store ----
#pragma unroll
    for (int i = 0; i < 4; i++) {
        lsum[i] += __shfl_xor_sync(0xffffffffu, lsum[i], 1);
        lsum[i] += __shfl_xor_sync(0xffffffffu, lsum[i], 2);
        lsum[i] = 1.0f / lsum[i];
    }

#pragma unroll
    for (int mt = 0; mt < 2; mt++) {
        int row0 = qbase + 32 * w + 16 * mt + r;
#pragma unroll
        for (int dn = 0; dn < 8; dn++) {
            float2 v0, v1;
            v0.x = o[mt][dn][0] * lsum[2 * mt];
            v0.y = o[mt][dn][1] * lsum[2 * mt];
            v1.x = o[mt][dn][2] * lsum[2 * mt + 1];
            v1.y = o[mt][dn][3] * lsum[2 * mt + 1];
            *(float2*)(og + (size_t)row0 * STRIDEF + 8 * dn + 2 * c) = v0;
            *(float2*)(og + (size_t)(row0 + 8) * STRIDEF + 8 * dn + 2 * c) = v1;
        }
    }
}

extern "C" void kernel_launch(void* const* d_in, const int* in_sizes, int n_in,
                              void* d_out, int out_size)
{
    const float*         q    = (const float*)d_in[0];
    const float*         k    = (const float*)d_in[1];
    const float*         v    = (const float*)d_in[2];
    const unsigned char* mask = (const unsigned char*)d_in[3];
    float*               out  = (float*)d_out;

    dim3 grid(SQ / MT, BB * HH);
    dpa_mma_kernel<<<grid, NTHREADS>>>(q, k, v, mask, out);
}